// round 2
// baseline (speedup 1.0000x reference)
#include <cuda_runtime.h>
#include <cstdint>

// Shapes: bs=8, h=w=32 (1024 positions), D=128, HEADS=8, PE=64, MAXP=32
#define SCALE 0.088388347648318447f   // 1/sqrt(128)

// ---- scratch (device globals; no allocations allowed) ----
__device__ float g_xn  [8*1024*128];            // layernormed x          (4 MB)
__device__ float g_q   [8*8*1024*128];          // Q[b][h][q'][d]         (32 MB)
__device__ float g_k   [8*8*1024*128];          // K[b][h][kv'][d]        (32 MB)
__device__ float g_rel [8*1024*8*64];           // [b][q'][h][row32|col32](16 MB)
__device__ float g_ctx [8*1024*8*128];          // ctx[b][q'][h*128+d]    (32 MB)
__device__ float g_probs_fb[67108864];          // fallback probs         (256 MB)
__device__ float g_out_fb[8*1024*128];          // fallback output

// =====================================================================
// 1) LayerNorm: one warp per row of 128
// =====================================================================
__global__ __launch_bounds__(256) void ln_kernel(const float* __restrict__ x,
                                                 const float* __restrict__ gam,
                                                 const float* __restrict__ bet) {
    int warp = threadIdx.x >> 5, lane = threadIdx.x & 31;
    int row = blockIdx.x * 8 + warp;              // 8192 rows
    const float4* xr = reinterpret_cast<const float4*>(x + (size_t)row * 128);
    float4 v = xr[lane];
    float s  = v.x + v.y + v.z + v.w;
    float sq = v.x*v.x + v.y*v.y + v.z*v.z + v.w*v.w;
    #pragma unroll
    for (int o = 16; o; o >>= 1) {
        s  += __shfl_xor_sync(0xffffffffu, s,  o);
        sq += __shfl_xor_sync(0xffffffffu, sq, o);
    }
    float mu  = s * (1.0f/128.0f);
    float var = sq * (1.0f/128.0f) - mu*mu;
    float inv = rsqrtf(var + 1e-5f);
    float4 g4 = reinterpret_cast<const float4*>(gam)[lane];
    float4 b4 = reinterpret_cast<const float4*>(bet)[lane];
    float4 o4;
    o4.x = (v.x - mu)*inv*g4.x + b4.x;
    o4.y = (v.y - mu)*inv*g4.y + b4.y;
    o4.z = (v.z - mu)*inv*g4.z + b4.z;
    o4.w = (v.w - mu)*inv*g4.w + b4.w;
    reinterpret_cast<float4*>(g_xn + (size_t)row*128)[lane] = o4;
}

// =====================================================================
// 2) Q/K projection GEMM. C[b][h][r][d] = sum_c xn[b][perm(r)][c] * W[h*128+d][c]
//    perm(r) = (r%32)*32 + r/32 (spatial transpose folded into row gather).
//    Block: 64 rows x 128 cols (one head), 256 threads, 8x4 per thread.
// =====================================================================
__global__ __launch_bounds__(256) void proj_kernel(const float* __restrict__ Wq,
                                                   const float* __restrict__ Wk) {
    __shared__ float At[32*68];    // [k][m], padded
    __shared__ float Bt[32*129];   // [k][n], padded (conflict-free)
    int mt = blockIdx.x;           // 0..127 over 8192 global rows
    int h  = blockIdx.y;           // 0..7
    const float* W = blockIdx.z ? Wk : Wq;
    float* C       = blockIdx.z ? g_k : g_q;
    int b  = (mt * 64) >> 10;
    int r0 = (mt * 64) & 1023;
    int tid = threadIdx.x, tx = tid & 31, ty = tid >> 5;
    int m0 = ty * 8;
    float acc[8][4] = {};
    for (int kc = 0; kc < 4; kc++) {
        __syncthreads();
        for (int idx = tid; idx < 64*32; idx += 256) {
            int i = idx >> 5, c = idx & 31;
            int r = r0 + i;
            int p = ((r & 31) << 5) | (r >> 5);
            At[c*68 + i] = g_xn[((size_t)b*1024 + p)*128 + kc*32 + c];
        }
        for (int idx = tid; idx < 128*32; idx += 256) {
            int o = idx >> 5, c = idx & 31;
            Bt[c*129 + o] = W[((size_t)(h*128 + o))*128 + kc*32 + c];
        }
        __syncthreads();
        #pragma unroll 8
        for (int k = 0; k < 32; k++) {
            float4 a0 = *reinterpret_cast<const float4*>(&At[k*68 + m0]);
            float4 a1 = *reinterpret_cast<const float4*>(&At[k*68 + m0 + 4]);
            float bb[4];
            #pragma unroll
            for (int j = 0; j < 4; j++) bb[j] = Bt[k*129 + tx + 32*j];
            float av[8] = {a0.x,a0.y,a0.z,a0.w,a1.x,a1.y,a1.z,a1.w};
            #pragma unroll
            for (int i = 0; i < 8; i++)
                #pragma unroll
                for (int j = 0; j < 4; j++)
                    acc[i][j] = fmaf(av[i], bb[j], acc[i][j]);
        }
    }
    #pragma unroll
    for (int i = 0; i < 8; i++) {
        size_t base = (((size_t)b*8 + h)*1024 + (size_t)(r0 + m0 + i))*128;
        #pragma unroll
        for (int j = 0; j < 4; j++) C[base + tx + 32*j] = acc[i][j];
    }
}

// =====================================================================
// 3) Relative-position terms. One warp per (b,h,q').
//    rowpart[k] = sum_{d<64}  Q[d]    * row_emb[k - I + 31][d]
//    colpart[l] = sum_{d<64}  Q[64+d] * col_emb[l - J + 31][d]
//    with I = q'%32 (=j), J = q'/32 (=i).
// =====================================================================
__global__ __launch_bounds__(256) void rel_kernel(const float* __restrict__ row_emb,
                                                  const float* __restrict__ col_emb) {
    __shared__ float qs[8][128];
    int warp = threadIdx.x >> 5, lane = threadIdx.x & 31;
    int wi = blockIdx.x * 8 + warp;                 // 0..65535
    int b = wi >> 13, h = (wi >> 10) & 7, q = wi & 1023;
    const float* Q = g_q + (((size_t)b*8 + h)*1024 + q)*128;
    reinterpret_cast<float4*>(qs[warp])[lane] = reinterpret_cast<const float4*>(Q)[lane];
    __syncwarp();
    int I = q & 31, J = q >> 5;
    const float* re = row_emb + (size_t)(lane - I + 31)*64;
    const float* ce = col_emb + (size_t)(lane - J + 31)*64;
    float ra = 0.f, ca = 0.f;
    #pragma unroll 8
    for (int d = 0; d < 64; d++) {
        ra = fmaf(qs[warp][d],      re[d], ra);
        ca = fmaf(qs[warp][64 + d], ce[d], ca);
    }
    float* dst = g_rel + (((size_t)b*1024 + q)*8 + h)*64;
    dst[lane]      = ra;
    dst[lane + 32] = ca;
}

// =====================================================================
// 4) Fused scores + softmax + probs write + context.
//    Block = (b, h, 32 queries). S[32][1024] lives in smem.
//    kv' = cc*128 + tx + 32*j  ->  v = tx, u = cc*4 + j  (rel epilogue)
// =====================================================================
__global__ __launch_bounds__(256, 1) void attn_kernel(float* __restrict__ probs) {
    extern __shared__ float sm[];
    float* S    = sm;                 // 32*1024
    float* Qs   = sm + 32*1024;       // [128][36]  (k-major, padded)
    float* KX   = Qs + 128*36;        // [128][129] K^T staging / [128][128] X staging
    float* relS = KX + 128*129;       // [32][64]

    int qt = blockIdx.x, h = blockIdx.y, b = blockIdx.z;
    int q0g = qt * 32;
    int tid = threadIdx.x, tx = tid & 31, ty = tid >> 5;
    int q0 = ty * 4;

    const float* Qbase = g_q + (((size_t)b*8 + h)*1024 + q0g)*128;
    for (int idx = tid; idx < 32*128; idx += 256) {
        int q = idx >> 7, d = idx & 127;
        Qs[d*36 + q] = Qbase[idx];
    }
    for (int idx = tid; idx < 32*64; idx += 256) {
        int q = idx >> 6, j = idx & 63;
        relS[idx] = g_rel[(((size_t)b*1024 + q0g + q)*8 + h)*64 + j];
    }

    // ---- scores: S[q][kv'] = (Q.K + row + col) * scale ----
    const float* Kbase = g_k + (((size_t)b*8 + h)*1024)*128;
    for (int cc = 0; cc < 8; cc++) {
        __syncthreads();
        for (int idx = tid; idx < 128*32; idx += 256) {
            int kv = idx >> 5, d4 = (idx & 31) * 4;
            float4 v = *reinterpret_cast<const float4*>(Kbase + (size_t)(cc*128 + kv)*128 + d4);
            KX[(d4+0)*129 + kv] = v.x;
            KX[(d4+1)*129 + kv] = v.y;
            KX[(d4+2)*129 + kv] = v.z;
            KX[(d4+3)*129 + kv] = v.w;
        }
        __syncthreads();
        float acc[4][4] = {};
        #pragma unroll 4
        for (int k = 0; k < 128; k++) {
            float4 qv = *reinterpret_cast<const float4*>(&Qs[k*36 + q0]);   // broadcast
            float k0 = KX[k*129 + tx];
            float k1 = KX[k*129 + tx + 32];
            float k2 = KX[k*129 + tx + 64];
            float k3 = KX[k*129 + tx + 96];
            acc[0][0]=fmaf(qv.x,k0,acc[0][0]); acc[0][1]=fmaf(qv.x,k1,acc[0][1]);
            acc[0][2]=fmaf(qv.x,k2,acc[0][2]); acc[0][3]=fmaf(qv.x,k3,acc[0][3]);
            acc[1][0]=fmaf(qv.y,k0,acc[1][0]); acc[1][1]=fmaf(qv.y,k1,acc[1][1]);
            acc[1][2]=fmaf(qv.y,k2,acc[1][2]); acc[1][3]=fmaf(qv.y,k3,acc[1][3]);
            acc[2][0]=fmaf(qv.z,k0,acc[2][0]); acc[2][1]=fmaf(qv.z,k1,acc[2][1]);
            acc[2][2]=fmaf(qv.z,k2,acc[2][2]); acc[2][3]=fmaf(qv.z,k3,acc[2][3]);
            acc[3][0]=fmaf(qv.w,k0,acc[3][0]); acc[3][1]=fmaf(qv.w,k1,acc[3][1]);
            acc[3][2]=fmaf(qv.w,k2,acc[3][2]); acc[3][3]=fmaf(qv.w,k3,acc[3][3]);
        }
        #pragma unroll
        for (int i = 0; i < 4; i++) {
            float rrow = relS[(q0+i)*64 + tx];
            float* srow = S + (q0+i)*1024 + cc*128 + tx;
            #pragma unroll
            for (int j = 0; j < 4; j++) {
                float rcol = relS[(q0+i)*64 + 32 + cc*4 + j];
                srow[32*j] = (acc[i][j] + rrow + rcol) * SCALE;
            }
        }
    }
    __syncthreads();

    // ---- softmax over 1024, write probs, keep normalized P in S ----
    for (int r = 0; r < 4; r++) {
        int q = ty*4 + r;
        float* row = S + q*1024;
        float mx = -1e30f;
        for (int i = tx; i < 1024; i += 32) mx = fmaxf(mx, row[i]);
        #pragma unroll
        for (int o = 16; o; o >>= 1) mx = fmaxf(mx, __shfl_xor_sync(0xffffffffu, mx, o));
        float sum = 0.f;
        for (int i = tx; i < 1024; i += 32) {
            float p = __expf(row[i] - mx);
            row[i] = p;
            sum += p;
        }
        #pragma unroll
        for (int o = 16; o; o >>= 1) sum += __shfl_xor_sync(0xffffffffu, sum, o);
        float inv = 1.0f / sum;
        float* prow = probs + (((size_t)b*1024 + q0g + q)*8 + h)*1024;
        for (int i = tx; i < 1024; i += 32) {
            float p = row[i] * inv;
            row[i] = p;
            prow[i] = p;
        }
    }
    __syncthreads();

    // ---- context: ctx[q][d] = sum_kv' P[q][kv'] * xn[b][kv'][d] ----
    float acc2[4][4] = {};
    const float* Xbase = g_xn + ((size_t)b*1024)*128;
    for (int cc = 0; cc < 8; cc++) {
        __syncthreads();
        for (int idx = tid; idx < 128*32; idx += 256) {
            reinterpret_cast<float4*>(KX)[idx] =
                reinterpret_cast<const float4*>(Xbase + (size_t)cc*128*128)[idx];
        }
        __syncthreads();
        const float* Sc = S + cc*128;
        #pragma unroll 2
        for (int kv = 0; kv < 128; kv++) {
            float4 xv = *reinterpret_cast<const float4*>(&KX[kv*128 + 4*tx]);
            float p0 = Sc[(q0+0)*1024 + kv];
            float p1 = Sc[(q0+1)*1024 + kv];
            float p2 = Sc[(q0+2)*1024 + kv];
            float p3 = Sc[(q0+3)*1024 + kv];
            acc2[0][0]=fmaf(p0,xv.x,acc2[0][0]); acc2[0][1]=fmaf(p0,xv.y,acc2[0][1]);
            acc2[0][2]=fmaf(p0,xv.z,acc2[0][2]); acc2[0][3]=fmaf(p0,xv.w,acc2[0][3]);
            acc2[1][0]=fmaf(p1,xv.x,acc2[1][0]); acc2[1][1]=fmaf(p1,xv.y,acc2[1][1]);
            acc2[1][2]=fmaf(p1,xv.z,acc2[1][2]); acc2[1][3]=fmaf(p1,xv.w,acc2[1][3]);
            acc2[2][0]=fmaf(p2,xv.x,acc2[2][0]); acc2[2][1]=fmaf(p2,xv.y,acc2[2][1]);
            acc2[2][2]=fmaf(p2,xv.z,acc2[2][2]); acc2[2][3]=fmaf(p2,xv.w,acc2[2][3]);
            acc2[3][0]=fmaf(p3,xv.x,acc2[3][0]); acc2[3][1]=fmaf(p3,xv.y,acc2[3][1]);
            acc2[3][2]=fmaf(p3,xv.z,acc2[3][2]); acc2[3][3]=fmaf(p3,xv.w,acc2[3][3]);
        }
    }
    #pragma unroll
    for (int i = 0; i < 4; i++) {
        float4 o4 = make_float4(acc2[i][0], acc2[i][1], acc2[i][2], acc2[i][3]);
        *reinterpret_cast<float4*>(g_ctx + (((size_t)b*1024 + q0g + q0 + i)*1024)
                                   + h*128 + 4*tx) = o4;
    }
}

// =====================================================================
// 5) Output GEMM: out[R][o] = sum_c ctx[R][c]*Wv[o][c] + bv[o] + xn[R][o]
//    M=8192, N=128, K=1024. Block 64x128, 256 threads, 8x4 per thread.
// =====================================================================
__global__ __launch_bounds__(256) void out_kernel(float* __restrict__ out,
                                                  const float* __restrict__ Wv,
                                                  const float* __restrict__ bvv) {
    __shared__ float At[32*68];
    __shared__ float Bt[32*129];
    int mt = blockIdx.x;  // 0..127
    int tid = threadIdx.x, tx = tid & 31, ty = tid >> 5;
    int m0 = ty * 8;
    float acc[8][4] = {};
    for (int kc = 0; kc < 32; kc++) {
        __syncthreads();
        for (int idx = tid; idx < 64*32; idx += 256) {
            int i = idx >> 5, c = idx & 31;
            At[c*68 + i] = g_ctx[(size_t)(mt*64 + i)*1024 + kc*32 + c];
        }
        for (int idx = tid; idx < 128*32; idx += 256) {
            int o = idx >> 5, c = idx & 31;
            Bt[c*129 + o] = Wv[(size_t)o*1024 + kc*32 + c];
        }
        __syncthreads();
        #pragma unroll 8
        for (int k = 0; k < 32; k++) {
            float4 a0 = *reinterpret_cast<const float4*>(&At[k*68 + m0]);
            float4 a1 = *reinterpret_cast<const float4*>(&At[k*68 + m0 + 4]);
            float bb[4];
            #pragma unroll
            for (int j = 0; j < 4; j++) bb[j] = Bt[k*129 + tx + 32*j];
            float av[8] = {a0.x,a0.y,a0.z,a0.w,a1.x,a1.y,a1.z,a1.w};
            #pragma unroll
            for (int i = 0; i < 8; i++)
                #pragma unroll
                for (int j = 0; j < 4; j++)
                    acc[i][j] = fmaf(av[i], bb[j], acc[i][j]);
        }
    }
    #pragma unroll
    for (int i = 0; i < 8; i++) {
        size_t R = (size_t)mt*64 + m0 + i;
        #pragma unroll
        for (int j = 0; j < 4; j++) {
            int o = tx + 32*j;
            out[R*128 + o] = acc[i][j] + bvv[o] + g_xn[R*128 + o];
        }
    }
}

// =====================================================================
extern "C" void kernel_launch(void* const* d_in, const int* in_sizes, int n_in,
                              void* d_out, int out_size) {
    (void)in_sizes; (void)n_in;
    const float* hidden  = (const float*)d_in[0];
    const float* row_emb = (const float*)d_in[1];
    const float* col_emb = (const float*)d_in[2];
    const float* Wq      = (const float*)d_in[3];
    const float* Wk      = (const float*)d_in[4];
    const float* Wv      = (const float*)d_in[5];
    const float* bv      = (const float*)d_in[6];
    const float* ln_g    = (const float*)d_in[7];
    const float* ln_b    = (const float*)d_in[8];

    float* out = (float*)d_out;
    float* outp;
    float* probs;
    const int OUT_ELEMS   = 1048576;
    const int PROBS_ELEMS = 67108864;
    if (out_size >= OUT_ELEMS + PROBS_ELEMS) {
        outp = out; probs = out + OUT_ELEMS;          // (output, probs) concatenated
    } else if (out_size == PROBS_ELEMS) {
        void* p = nullptr; cudaGetSymbolAddress(&p, g_out_fb);
        outp = (float*)p; probs = out;                // probs only
    } else {
        void* p = nullptr; cudaGetSymbolAddress(&p, g_probs_fb);
        outp = out; probs = (float*)p;                // output only
    }

    const int ATTN_SMEM = (32*1024 + 128*36 + 128*129 + 32*64) * 4;  // 223744 B
    cudaFuncSetAttribute(attn_kernel, cudaFuncAttributeMaxDynamicSharedMemorySize,
                         ATTN_SMEM);

    ln_kernel  <<<1024, 256>>>(hidden, ln_g, ln_b);
    proj_kernel<<<dim3(128, 8, 2), 256>>>(Wq, Wk);
    rel_kernel <<<8192, 256>>>(row_emb, col_emb);
    attn_kernel<<<dim3(32, 8, 8), 256, ATTN_SMEM>>>(probs);
    out_kernel <<<128, 256>>>(outp, Wv, bv);
}

// round 5
// speedup vs baseline: 1.1409x; 1.1409x over previous
#include <cuda_runtime.h>
#include <cstdint>

#define SCALE 0.088388347648318447f   // 1/sqrt(128)

using ull = unsigned long long;

__device__ __forceinline__ ull dup2(float s) {
    ull r; asm("mov.b64 %0, {%1, %1};" : "=l"(r) : "f"(s)); return r;
}
__device__ __forceinline__ void fma2(ull& a, ull x, ull y) {
    asm("fma.rn.f32x2 %0, %1, %2, %0;" : "+l"(a) : "l"(x), "l"(y));
}
__device__ __forceinline__ float2 up2(ull a) {
    float2 f; asm("mov.b64 {%0, %1}, %2;" : "=f"(f.x), "=f"(f.y) : "l"(a)); return f;
}

// ---- scratch (device globals; no allocations allowed) ----
__device__ float g_xn  [8*1024*128];
__device__ float g_q   [8*8*1024*128];          // Q[b][h][q'][d]
__device__ float g_k   [8*8*1024*128];          // K[b][h][kv'][d]
__device__ float g_kt  [8*8*128*1024];          // K^T[b][h][d][kv']
__device__ float g_rel [8*1024*8*64];           // [b][q'][h][row32|col32]
__device__ float g_ctx [8*1024*8*128];          // ctx[(b*1024+q')*1024 + h*128+d]
__device__ float g_probs_fb[67108864];
__device__ float g_out_fb[8*1024*128];

// =====================================================================
// 1) LayerNorm
// =====================================================================
__global__ __launch_bounds__(256) void ln_kernel(const float* __restrict__ x,
                                                 const float* __restrict__ gam,
                                                 const float* __restrict__ bet) {
    int warp = threadIdx.x >> 5, lane = threadIdx.x & 31;
    int row = blockIdx.x * 8 + warp;
    float4 v = reinterpret_cast<const float4*>(x + (size_t)row * 128)[lane];
    float s  = v.x + v.y + v.z + v.w;
    float sq = v.x*v.x + v.y*v.y + v.z*v.z + v.w*v.w;
    #pragma unroll
    for (int o = 16; o; o >>= 1) {
        s  += __shfl_xor_sync(0xffffffffu, s,  o);
        sq += __shfl_xor_sync(0xffffffffu, sq, o);
    }
    float mu  = s * (1.0f/128.0f);
    float var = sq * (1.0f/128.0f) - mu*mu;
    float inv = rsqrtf(var + 1e-5f);
    float4 g4 = reinterpret_cast<const float4*>(gam)[lane];
    float4 b4 = reinterpret_cast<const float4*>(bet)[lane];
    float4 o4;
    o4.x = (v.x - mu)*inv*g4.x + b4.x;
    o4.y = (v.y - mu)*inv*g4.y + b4.y;
    o4.z = (v.z - mu)*inv*g4.z + b4.z;
    o4.w = (v.w - mu)*inv*g4.w + b4.w;
    reinterpret_cast<float4*>(g_xn + (size_t)row*128)[lane] = o4;
}

// =====================================================================
// 2) Q/K projection GEMM (f32x2 over m-pairs)
// =====================================================================
__global__ __launch_bounds__(256) void proj_kernel(const float* __restrict__ Wq,
                                                   const float* __restrict__ Wk) {
    __shared__ float At[32*68];
    __shared__ float Bt[32*129];
    int mt = blockIdx.x, h = blockIdx.y;
    const float* W = blockIdx.z ? Wk : Wq;
    float* C       = blockIdx.z ? g_k : g_q;
    int b  = (mt * 64) >> 10;
    int r0 = (mt * 64) & 1023;
    int tid = threadIdx.x, tx = tid & 31, ty = tid >> 5;
    int m0 = ty * 8;
    ull acc[4][4];
    #pragma unroll
    for (int p = 0; p < 4; p++)
        #pragma unroll
        for (int j = 0; j < 4; j++) acc[p][j] = 0ull;
    for (int kc = 0; kc < 4; kc++) {
        __syncthreads();
        for (int idx = tid; idx < 64*32; idx += 256) {
            int i = idx >> 5, c = idx & 31;
            int r = r0 + i;
            int p = ((r & 31) << 5) | (r >> 5);
            At[c*68 + i] = g_xn[((size_t)b*1024 + p)*128 + kc*32 + c];
        }
        for (int idx = tid; idx < 128*32; idx += 256) {
            int o = idx >> 5, c = idx & 31;
            Bt[c*129 + o] = W[((size_t)(h*128 + o))*128 + kc*32 + c];
        }
        __syncthreads();
        #pragma unroll 4
        for (int k = 0; k < 32; k++) {
            ulonglong2 aA = *reinterpret_cast<const ulonglong2*>(&At[k*68 + m0]);
            ulonglong2 aB = *reinterpret_cast<const ulonglong2*>(&At[k*68 + m0 + 4]);
            #pragma unroll
            for (int j = 0; j < 4; j++) {
                ull dj = dup2(Bt[k*129 + tx + 32*j]);
                fma2(acc[0][j], aA.x, dj);
                fma2(acc[1][j], aA.y, dj);
                fma2(acc[2][j], aB.x, dj);
                fma2(acc[3][j], aB.y, dj);
            }
        }
    }
    #pragma unroll
    for (int p = 0; p < 4; p++) {
        size_t base0 = (((size_t)b*8 + h)*1024 + (size_t)(r0 + m0 + 2*p))*128;
        #pragma unroll
        for (int j = 0; j < 4; j++) {
            float2 f = up2(acc[p][j]);
            C[base0 + tx + 32*j]       = f.x;
            C[base0 + 128 + tx + 32*j] = f.y;
        }
    }
}

// =====================================================================
// 2b) Transpose K -> KT (per (b,h): [1024][128] -> [128][1024])
// =====================================================================
__global__ __launch_bounds__(256) void transpose_kernel() {
    __shared__ float T[32][33];
    int bh = blockIdx.z;
    int d0 = blockIdx.x * 32;
    int kv0 = blockIdx.y * 32;
    int tx = threadIdx.x & 31, ty = threadIdx.x >> 5;
    #pragma unroll
    for (int r = 0; r < 4; r++)
        T[ty + 8*r][tx] = g_k[((size_t)bh*1024 + kv0 + ty + 8*r)*128 + d0 + tx];
    __syncthreads();
    #pragma unroll
    for (int r = 0; r < 4; r++)
        g_kt[((size_t)bh*128 + d0 + ty + 8*r)*1024 + kv0 + tx] = T[tx][ty + 8*r];
}

// =====================================================================
// 3) Relative-position terms. One warp per (b,h,q').
// =====================================================================
__global__ __launch_bounds__(256) void rel_kernel(const float* __restrict__ row_emb,
                                                  const float* __restrict__ col_emb) {
    __shared__ float qs[8][128];
    int warp = threadIdx.x >> 5, lane = threadIdx.x & 31;
    int wi = blockIdx.x * 8 + warp;
    int b = wi >> 13, h = (wi >> 10) & 7, q = wi & 1023;
    const float* Q = g_q + (((size_t)b*8 + h)*1024 + q)*128;
    reinterpret_cast<float4*>(qs[warp])[lane] = reinterpret_cast<const float4*>(Q)[lane];
    __syncwarp();
    int I = q & 31, J = q >> 5;
    const float* re = row_emb + (size_t)(lane - I + 31)*64;
    const float* ce = col_emb + (size_t)(lane - J + 31)*64;
    float ra = 0.f, ca = 0.f;
    #pragma unroll 8
    for (int d = 0; d < 64; d++) {
        ra = fmaf(qs[warp][d],      re[d], ra);
        ca = fmaf(qs[warp][64 + d], ce[d], ca);
    }
    float* dst = g_rel + (((size_t)b*1024 + q)*8 + h)*64;
    dst[lane]      = ra;
    dst[lane + 32] = ca;
}

// =====================================================================
// 4) Fused attention: 512 threads, 32 queries per block, f32x2 math.
//    smem floats: S[32][1025]@0, Qs[128][36]@32800, relS[32][64]@37408,
//    KX[128][132]@39456 (K / X staging, then ctx-partial overlay)
// =====================================================================
__global__ __launch_bounds__(512, 1) void attn_kernel(float* __restrict__ probs) {
    extern __shared__ float sm[];
    float* S    = sm;
    float* Qs   = sm + 32800;
    float* relS = sm + 37408;
    float* KX   = sm + 39456;

    int qt = blockIdx.x, h = blockIdx.y, b = blockIdx.z;
    int q0g = qt * 32;
    int tid = threadIdx.x, tx = tid & 31, w = tid >> 5;   // 16 warps
    int qg = w & 3, kvq = w >> 2;                         // 4 q-groups x 4 kv-quarters

    // ---- stage Q (k-major) and rel terms ----
    const float* Qbase = g_q + (((size_t)b*8 + h)*1024 + q0g)*128;
    for (int f = tid; f < 32*32; f += 512) {
        int d4 = f & 31, q = f >> 5;
        float4 v = *reinterpret_cast<const float4*>(Qbase + (size_t)q*128 + 4*d4);
        Qs[(4*d4+0)*36 + q] = v.x;
        Qs[(4*d4+1)*36 + q] = v.y;
        Qs[(4*d4+2)*36 + q] = v.z;
        Qs[(4*d4+3)*36 + q] = v.w;
    }
    for (int f = tid; f < 32*64; f += 512) {
        int q = f >> 6, j = f & 63;
        relS[f] = g_rel[(((size_t)b*1024 + q0g + q)*8 + h)*64 + j];
    }

    // ---- scores: each warp does 8 q x 32 kv per 128-kv section ----
    const float* KTb = g_kt + ((size_t)(b*8 + h))*128*1024;
    const float* qp = Qs + qg*8;
    for (int sec = 0; sec < 8; sec++) {
        __syncthreads();
        for (int f = tid; f < 128*32; f += 512) {
            int kv4 = f & 31, d = f >> 5;
            float4 v = *reinterpret_cast<const float4*>(KTb + (size_t)d*1024 + sec*128 + 4*kv4);
            *reinterpret_cast<float4*>(&KX[d*132 + 4*kv4]) = v;
        }
        __syncthreads();
        ull a0 = 0, a1 = 0, a2 = 0, a3 = 0;
        const float* kp = KX + kvq*32 + tx;
        #pragma unroll 8
        for (int d = 0; d < 128; d++) {
            ulonglong2 qA = *reinterpret_cast<const ulonglong2*>(qp + d*36);
            ulonglong2 qB = *reinterpret_cast<const ulonglong2*>(qp + d*36 + 4);
            ull kd = dup2(kp[d*132]);
            fma2(a0, qA.x, kd); fma2(a1, qA.y, kd);
            fma2(a2, qB.x, kd); fma2(a3, qB.y, kd);
        }
        float sc[8];
        { float2 t = up2(a0); sc[0]=t.x; sc[1]=t.y; }
        { float2 t = up2(a1); sc[2]=t.x; sc[3]=t.y; }
        { float2 t = up2(a2); sc[4]=t.x; sc[5]=t.y; }
        { float2 t = up2(a3); sc[6]=t.x; sc[7]=t.y; }
        int u  = sec*4 + kvq;
        int kv = sec*128 + kvq*32 + tx;
        #pragma unroll
        for (int k = 0; k < 8; k++) {
            int q = qg*8 + k;
            S[q*1025 + kv] = (sc[k] + relS[q*64 + tx] + relS[q*64 + 32 + u]) * SCALE;
        }
    }
    __syncthreads();

    // ---- softmax: one warp per 2 rows; write probs; keep P in S ----
    {
        float* r1 = S + w*1025;
        float* r2 = S + (w+16)*1025;
        float m1 = -1e30f, m2 = -1e30f;
        #pragma unroll 4
        for (int t = 0; t < 32; t++) {
            m1 = fmaxf(m1, r1[tx + 32*t]);
            m2 = fmaxf(m2, r2[tx + 32*t]);
        }
        #pragma unroll
        for (int o = 16; o; o >>= 1) {
            m1 = fmaxf(m1, __shfl_xor_sync(0xffffffffu, m1, o));
            m2 = fmaxf(m2, __shfl_xor_sync(0xffffffffu, m2, o));
        }
        float s1 = 0.f, s2 = 0.f;
        #pragma unroll 4
        for (int t = 0; t < 32; t++) {
            float p1 = __expf(r1[tx + 32*t] - m1); r1[tx + 32*t] = p1; s1 += p1;
            float p2 = __expf(r2[tx + 32*t] - m2); r2[tx + 32*t] = p2; s2 += p2;
        }
        #pragma unroll
        for (int o = 16; o; o >>= 1) {
            s1 += __shfl_xor_sync(0xffffffffu, s1, o);
            s2 += __shfl_xor_sync(0xffffffffu, s2, o);
        }
        float i1 = 1.0f / s1, i2 = 1.0f / s2;
        float* p1r = probs + (((size_t)b*1024 + q0g + w)*8 + h)*1024;
        float* p2r = probs + (((size_t)b*1024 + q0g + w + 16)*8 + h)*1024;
        #pragma unroll 4
        for (int t = 0; t < 32; t++) {
            float p1 = r1[tx + 32*t] * i1; r1[tx + 32*t] = p1; p1r[tx + 32*t] = p1;
            float p2 = r2[tx + 32*t] * i2; r2[tx + 32*t] = p2; p2r[tx + 32*t] = p2;
        }
    }

    // ---- context: warp = (qg, kvq); thread owns d = 4tx..4tx+3 for 8 q ----
    ull c2[8][2];
    #pragma unroll
    for (int k = 0; k < 8; k++) { c2[k][0] = 0ull; c2[k][1] = 0ull; }
    const float* Xbase = g_xn + ((size_t)b*1024)*128;
    for (int sec = 0; sec < 8; sec++) {
        __syncthreads();
        for (int f = tid; f < 128*32; f += 512) {
            int d4 = f & 31, kv = f >> 5;
            float4 v = *reinterpret_cast<const float4*>(Xbase + (size_t)(sec*128 + kv)*128 + 4*d4);
            *reinterpret_cast<float4*>(&KX[kv*132 + 4*d4]) = v;
        }
        __syncthreads();
        const float* Srow = S + sec*128 + kvq*32;
        #pragma unroll 4
        for (int kvi = 0; kvi < 32; kvi++) {
            ulonglong2 xv = *reinterpret_cast<const ulonglong2*>(&KX[(kvq*32 + kvi)*132 + 4*tx]);
            #pragma unroll
            for (int k = 0; k < 8; k++) {
                ull pd = dup2(Srow[(qg*8 + k)*1025 + kvi]);
                fma2(c2[k][0], pd, xv.x);
                fma2(c2[k][1], pd, xv.y);
            }
        }
    }
    // ---- reduce 4 kv-quarter partials via smem overlay on KX ----
    __syncthreads();
    #pragma unroll
    for (int k = 0; k < 8; k++) {
        float2 lo = up2(c2[k][0]);
        float2 hi = up2(c2[k][1]);
        *reinterpret_cast<float4*>(&KX[((qg*4 + kvq)*8 + k)*128 + 4*tx]) =
            make_float4(lo.x, lo.y, hi.x, hi.y);
    }
    __syncthreads();
    #pragma unroll
    for (int rr = 0; rr < 2; rr++) {
        int q = 2*w + rr;
        int qg2 = q >> 3, k2 = q & 7;
        float4 s0 = *reinterpret_cast<const float4*>(&KX[((qg2*4+0)*8 + k2)*128 + 4*tx]);
        float4 s1 = *reinterpret_cast<const float4*>(&KX[((qg2*4+1)*8 + k2)*128 + 4*tx]);
        float4 s2 = *reinterpret_cast<const float4*>(&KX[((qg2*4+2)*8 + k2)*128 + 4*tx]);
        float4 s3 = *reinterpret_cast<const float4*>(&KX[((qg2*4+3)*8 + k2)*128 + 4*tx]);
        float4 o4 = make_float4(s0.x+s1.x+s2.x+s3.x, s0.y+s1.y+s2.y+s3.y,
                                s0.z+s1.z+s2.z+s3.z, s0.w+s1.w+s2.w+s3.w);
        *reinterpret_cast<float4*>(g_ctx + ((size_t)(b*1024 + q0g + q))*1024
                                   + h*128 + 4*tx) = o4;
    }
}

// =====================================================================
// 5) Output GEMM (f32x2): out = ctx @ Wv^T + bv + xn
// =====================================================================
__global__ __launch_bounds__(256) void out_kernel(float* __restrict__ out,
                                                  const float* __restrict__ Wv,
                                                  const float* __restrict__ bvv) {
    __shared__ float At[32*68];
    __shared__ float Bt[32*129];
    int mt = blockIdx.x;
    int tid = threadIdx.x, tx = tid & 31, ty = tid >> 5;
    int m0 = ty * 8;
    ull acc[4][4];
    #pragma unroll
    for (int p = 0; p < 4; p++)
        #pragma unroll
        for (int j = 0; j < 4; j++) acc[p][j] = 0ull;
    for (int kc = 0; kc < 32; kc++) {
        __syncthreads();
        for (int idx = tid; idx < 64*32; idx += 256) {
            int i = idx >> 5, c = idx & 31;
            At[c*68 + i] = g_ctx[(size_t)(mt*64 + i)*1024 + kc*32 + c];
        }
        for (int idx = tid; idx < 128*32; idx += 256) {
            int o = idx >> 5, c = idx & 31;
            Bt[c*129 + o] = Wv[(size_t)o*1024 + kc*32 + c];
        }
        __syncthreads();
        #pragma unroll 4
        for (int k = 0; k < 32; k++) {
            ulonglong2 aA = *reinterpret_cast<const ulonglong2*>(&At[k*68 + m0]);
            ulonglong2 aB = *reinterpret_cast<const ulonglong2*>(&At[k*68 + m0 + 4]);
            #pragma unroll
            for (int j = 0; j < 4; j++) {
                ull dj = dup2(Bt[k*129 + tx + 32*j]);
                fma2(acc[0][j], aA.x, dj);
                fma2(acc[1][j], aA.y, dj);
                fma2(acc[2][j], aB.x, dj);
                fma2(acc[3][j], aB.y, dj);
            }
        }
    }
    #pragma unroll
    for (int p = 0; p < 4; p++) {
        size_t R0 = (size_t)mt*64 + m0 + 2*p;
        #pragma unroll
        for (int j = 0; j < 4; j++) {
            int o = tx + 32*j;
            float2 f = up2(acc[p][j]);
            out[R0*128 + o]       = f.x + bvv[o] + g_xn[R0*128 + o];
            out[(R0+1)*128 + o]   = f.y + bvv[o] + g_xn[(R0+1)*128 + o];
        }
    }
}

// =====================================================================
extern "C" void kernel_launch(void* const* d_in, const int* in_sizes, int n_in,
                              void* d_out, int out_size) {
    (void)in_sizes; (void)n_in;
    const float* hidden  = (const float*)d_in[0];
    const float* row_emb = (const float*)d_in[1];
    const float* col_emb = (const float*)d_in[2];
    const float* Wq      = (const float*)d_in[3];
    const float* Wk      = (const float*)d_in[4];
    const float* Wv      = (const float*)d_in[5];
    const float* bv      = (const float*)d_in[6];
    const float* ln_g    = (const float*)d_in[7];
    const float* ln_b    = (const float*)d_in[8];

    float* out = (float*)d_out;
    float* outp;
    float* probs;
    const int OUT_ELEMS   = 1048576;
    const int PROBS_ELEMS = 67108864;
    if (out_size >= OUT_ELEMS + PROBS_ELEMS) {
        outp = out; probs = out + OUT_ELEMS;
    } else if (out_size == PROBS_ELEMS) {
        void* p = nullptr; cudaGetSymbolAddress(&p, g_out_fb);
        outp = (float*)p; probs = out;
    } else {
        void* p = nullptr; cudaGetSymbolAddress(&p, g_probs_fb);
        outp = out; probs = (float*)p;
    }

    const int ATTN_SMEM = (32*1025 + 128*36 + 32*64 + 128*132) * 4;  // 225408 B
    cudaFuncSetAttribute(attn_kernel, cudaFuncAttributeMaxDynamicSharedMemorySize,
                         ATTN_SMEM);

    ln_kernel       <<<1024, 256>>>(hidden, ln_g, ln_b);
    proj_kernel     <<<dim3(128, 8, 2), 256>>>(Wq, Wk);
    transpose_kernel<<<dim3(4, 32, 64), 256>>>();
    rel_kernel      <<<8192, 256>>>(row_emb, col_emb);
    attn_kernel     <<<dim3(32, 8, 8), 512, ATTN_SMEM>>>(probs);
    out_kernel      <<<128, 256>>>(outp, Wv, bv);
}